// round 1
// baseline (speedup 1.0000x reference)
#include <cuda_runtime.h>
#include <cuda_bf16.h>
#include <cstdint>

// GraphSAGE 2-layer, fp32.
//   p1|q1 = x @ [W_l1 | W_r1]^T          (GEMM1, [N,128] out)
//   s1    = scatter-add p1[src] at dst ; deg = scatter-add 1
//   h     = relu(s1/max(deg,1) + b1 + q1)
//   s2    = scatter-add h[src] at dst
//   out   = [s2/deg | h] @ [W_l2 | W_r2]^T + b2   (GEMM2)

#define NMAX 100000

__device__ __align__(16) float g_pq  [(size_t)NMAX * 128];  // p1 (cols 0..63) | q1 (64..127)
__device__ __align__(16) float g_s1  [(size_t)NMAX * 64];
__device__ __align__(16) float g_h   [(size_t)NMAX * 64];
__device__ __align__(16) float g_s2  [(size_t)NMAX * 64];
__device__ __align__(16) float g_deg [NMAX];
__device__ __align__(16) float g_rdeg[NMAX];

// ---------------------------------------------------------------------------
// zero accumulators
// ---------------------------------------------------------------------------
__global__ void zero_kernel(int N) {
    int gid = blockIdx.x * 256 + threadIdx.x;           // N*16 threads
    float4 z = make_float4(0.f, 0.f, 0.f, 0.f);
    int n16 = N * 16;
    if (gid < n16) {
        reinterpret_cast<float4*>(g_s1)[gid] = z;
        reinterpret_cast<float4*>(g_s2)[gid] = z;
    }
    if (gid < (N + 3) / 4) {
        reinterpret_cast<float4*>(g_deg)[gid] = z;
    }
}

// ---------------------------------------------------------------------------
// Tiled fp32 GEMM: BM=128, BN=128, BK=32, 256 threads, 8x8 microtile
// ---------------------------------------------------------------------------
#define BM 128
#define BN 128
#define BK 32
#define LDA (BM + 4)
#define LDB (BN + 4)

// GEMM1: g_pq[m, n] = sum_k x[m,k] * Wc[n,k],  Wc = [W_l1 ; W_r1] stacked rows
__global__ __launch_bounds__(256) void gemm1_kernel(
    const float* __restrict__ x,
    const float* __restrict__ Wl, const float* __restrict__ Wr, int N)
{
    __shared__ float Xs[BK * LDA];
    __shared__ float Ws[BK * LDB];
    int tid = threadIdx.x;
    int m0  = blockIdx.x * BM;
    int ty  = tid >> 4, tx = tid & 15;
    float acc[8][8];
#pragma unroll
    for (int i = 0; i < 8; i++)
#pragma unroll
        for (int j = 0; j < 8; j++) acc[i][j] = 0.f;

    for (int kc = 0; kc < 128; kc += BK) {
#pragma unroll
        for (int i = 0; i < 4; i++) {
            int f = tid + i * 256;           // 0..1023
            int m = f >> 3;                  // 0..127
            int c4 = f & 7;                  // 0..7
            float4 v = make_float4(0.f, 0.f, 0.f, 0.f);
            int gm = m0 + m;
            if (gm < N)
                v = *reinterpret_cast<const float4*>(x + (size_t)gm * 128 + kc + c4 * 4);
            int kk = c4 * 4;
            Xs[(kk + 0) * LDA + m] = v.x;
            Xs[(kk + 1) * LDA + m] = v.y;
            Xs[(kk + 2) * LDA + m] = v.z;
            Xs[(kk + 3) * LDA + m] = v.w;
        }
#pragma unroll
        for (int i = 0; i < 4; i++) {
            int f = tid + i * 256;
            int n = f >> 3;
            int c4 = f & 7;
            const float* Wsrc = (n < 64) ? (Wl + (size_t)n * 128)
                                         : (Wr + (size_t)(n - 64) * 128);
            float4 v = *reinterpret_cast<const float4*>(Wsrc + kc + c4 * 4);
            int kk = c4 * 4;
            Ws[(kk + 0) * LDB + n] = v.x;
            Ws[(kk + 1) * LDB + n] = v.y;
            Ws[(kk + 2) * LDB + n] = v.z;
            Ws[(kk + 3) * LDB + n] = v.w;
        }
        __syncthreads();
#pragma unroll
        for (int k = 0; k < BK; k++) {
            float a[8], b[8];
            *reinterpret_cast<float4*>(&a[0]) = *reinterpret_cast<const float4*>(&Xs[k * LDA + ty * 8]);
            *reinterpret_cast<float4*>(&a[4]) = *reinterpret_cast<const float4*>(&Xs[k * LDA + ty * 8 + 4]);
            *reinterpret_cast<float4*>(&b[0]) = *reinterpret_cast<const float4*>(&Ws[k * LDB + tx * 8]);
            *reinterpret_cast<float4*>(&b[4]) = *reinterpret_cast<const float4*>(&Ws[k * LDB + tx * 8 + 4]);
#pragma unroll
            for (int i = 0; i < 8; i++)
#pragma unroll
                for (int j = 0; j < 8; j++) acc[i][j] += a[i] * b[j];
        }
        __syncthreads();
    }
#pragma unroll
    for (int i = 0; i < 8; i++) {
        int gm = m0 + ty * 8 + i;
        if (gm < N) {
#pragma unroll
            for (int j = 0; j < 8; j += 4) {
                *reinterpret_cast<float4*>(g_pq + (size_t)gm * 128 + tx * 8 + j) =
                    make_float4(acc[i][j], acc[i][j + 1], acc[i][j + 2], acc[i][j + 3]);
            }
        }
    }
}

// GEMM2: out[m, n] = sum_c A[m,c] * Wc2[n,c] + b2[n]
//   A cols 0..63 = g_s2 * g_rdeg, cols 64..127 = g_h
//   Wc2 cols 0..63 from W_l2, 64..127 from W_r2
__global__ __launch_bounds__(256) void gemm2_kernel(
    const float* __restrict__ Wl, const float* __restrict__ Wr,
    const float* __restrict__ bias, float* __restrict__ out, int N)
{
    __shared__ float Xs[BK * LDA];
    __shared__ float Ws[BK * LDB];
    int tid = threadIdx.x;
    int m0  = blockIdx.x * BM;
    int ty  = tid >> 4, tx = tid & 15;
    float acc[8][8];
#pragma unroll
    for (int i = 0; i < 8; i++)
#pragma unroll
        for (int j = 0; j < 8; j++) acc[i][j] = 0.f;

    for (int kc = 0; kc < 128; kc += BK) {
        bool first = (kc < 64);
        int coff = first ? kc : (kc - 64);
        const float* Asrc = first ? g_s2 : g_h;
#pragma unroll
        for (int i = 0; i < 4; i++) {
            int f = tid + i * 256;
            int m = f >> 3;
            int c4 = f & 7;
            float4 v = make_float4(0.f, 0.f, 0.f, 0.f);
            int gm = m0 + m;
            if (gm < N) {
                v = *reinterpret_cast<const float4*>(Asrc + (size_t)gm * 64 + coff + c4 * 4);
                if (first) {
                    float r = g_rdeg[gm];
                    v.x *= r; v.y *= r; v.z *= r; v.w *= r;
                }
            }
            int kk = c4 * 4;
            Xs[(kk + 0) * LDA + m] = v.x;
            Xs[(kk + 1) * LDA + m] = v.y;
            Xs[(kk + 2) * LDA + m] = v.z;
            Xs[(kk + 3) * LDA + m] = v.w;
        }
        const float* Wsrc = first ? Wl : Wr;
#pragma unroll
        for (int i = 0; i < 4; i++) {
            int f = tid + i * 256;
            int n = f >> 3;
            int c4 = f & 7;
            float4 v = *reinterpret_cast<const float4*>(Wsrc + (size_t)n * 64 + coff + c4 * 4);
            int kk = c4 * 4;
            Ws[(kk + 0) * LDB + n] = v.x;
            Ws[(kk + 1) * LDB + n] = v.y;
            Ws[(kk + 2) * LDB + n] = v.z;
            Ws[(kk + 3) * LDB + n] = v.w;
        }
        __syncthreads();
#pragma unroll
        for (int k = 0; k < BK; k++) {
            float a[8], b[8];
            *reinterpret_cast<float4*>(&a[0]) = *reinterpret_cast<const float4*>(&Xs[k * LDA + ty * 8]);
            *reinterpret_cast<float4*>(&a[4]) = *reinterpret_cast<const float4*>(&Xs[k * LDA + ty * 8 + 4]);
            *reinterpret_cast<float4*>(&b[0]) = *reinterpret_cast<const float4*>(&Ws[k * LDB + tx * 8]);
            *reinterpret_cast<float4*>(&b[4]) = *reinterpret_cast<const float4*>(&Ws[k * LDB + tx * 8 + 4]);
#pragma unroll
            for (int i = 0; i < 8; i++)
#pragma unroll
                for (int j = 0; j < 8; j++) acc[i][j] += a[i] * b[j];
        }
        __syncthreads();
    }
#pragma unroll
    for (int i = 0; i < 8; i++) {
        int gm = m0 + ty * 8 + i;
        if (gm < N) {
#pragma unroll
            for (int j = 0; j < 8; j += 4) {
                float4 bb = *reinterpret_cast<const float4*>(bias + tx * 8 + j);
                *reinterpret_cast<float4*>(out + (size_t)gm * 128 + tx * 8 + j) =
                    make_float4(acc[i][j] + bb.x, acc[i][j + 1] + bb.y,
                                acc[i][j + 2] + bb.z, acc[i][j + 3] + bb.w);
            }
        }
    }
}

// ---------------------------------------------------------------------------
// scatter: 16 threads per edge, red.global.add.v4.f32 (16B vector atomics)
// LAYER 1: feat = g_pq (stride 128, p1 = first 64), out = g_s1, also count deg
// LAYER 2: feat = g_h  (stride 64),                 out = g_s2
// ---------------------------------------------------------------------------
template <int LAYER>
__global__ void scatter_kernel(const int* __restrict__ ei, int E) {
    int gid = blockIdx.x * 256 + threadIdx.x;
    int e = gid >> 4;
    if (e >= E) return;
    int part = gid & 15;
    int s = __ldg(ei + e);
    int d = __ldg(ei + E + e);
    const float* feat = (LAYER == 1) ? g_pq : g_h;
    const int stride  = (LAYER == 1) ? 128 : 64;
    float4 v = *reinterpret_cast<const float4*>(feat + (size_t)s * stride + part * 4);
    float* outp = ((LAYER == 1) ? g_s1 : g_s2) + (size_t)d * 64 + part * 4;
    asm volatile("red.global.add.v4.f32 [%0], {%1,%2,%3,%4};"
                 :: "l"(outp), "f"(v.x), "f"(v.y), "f"(v.z), "f"(v.w) : "memory");
    if (LAYER == 1 && part == 0)
        atomicAdd(&g_deg[d], 1.0f);
}

// ---------------------------------------------------------------------------
// h = relu(s1/max(deg,1) + b1 + q1) ; also store rdeg = 1/max(deg,1)
// ---------------------------------------------------------------------------
__global__ void h_kernel(const float* __restrict__ b1, int N) {
    int gid = blockIdx.x * 256 + threadIdx.x;   // N*16 threads
    int node = gid >> 4;
    if (node >= N) return;
    int part = gid & 15;
    float r = 1.0f / fmaxf(g_deg[node], 1.0f);
    if (part == 0) g_rdeg[node] = r;
    float4 sv = *reinterpret_cast<const float4*>(g_s1 + (size_t)node * 64 + part * 4);
    float4 qv = *reinterpret_cast<const float4*>(g_pq + (size_t)node * 128 + 64 + part * 4);
    float4 bv = *reinterpret_cast<const float4*>(b1 + part * 4);
    float4 hv;
    hv.x = fmaxf(sv.x * r + bv.x + qv.x, 0.f);
    hv.y = fmaxf(sv.y * r + bv.y + qv.y, 0.f);
    hv.z = fmaxf(sv.z * r + bv.z + qv.z, 0.f);
    hv.w = fmaxf(sv.w * r + bv.w + qv.w, 0.f);
    *reinterpret_cast<float4*>(g_h + (size_t)node * 64 + part * 4) = hv;
}

// ---------------------------------------------------------------------------
extern "C" void kernel_launch(void* const* d_in, const int* in_sizes, int n_in,
                              void* d_out, int out_size)
{
    const float* x   = (const float*)d_in[0];
    const int*   ei  = (const int*)  d_in[1];
    const float* Wl1 = (const float*)d_in[2];
    const float* Wr1 = (const float*)d_in[3];
    const float* b1  = (const float*)d_in[4];
    const float* Wl2 = (const float*)d_in[5];
    const float* Wr2 = (const float*)d_in[6];
    const float* b2  = (const float*)d_in[7];
    float* out = (float*)d_out;

    int N = in_sizes[0] / 128;
    int E = in_sizes[1] / 2;

    int zgrid = (N * 16 + 255) / 256;
    int ggrid = (N + BM - 1) / BM;
    long sthreads = (long)E * 16;
    int sgrid = (int)((sthreads + 255) / 256);

    zero_kernel<<<zgrid, 256>>>(N);
    gemm1_kernel<<<ggrid, 256>>>(x, Wl1, Wr1, N);
    scatter_kernel<1><<<sgrid, 256>>>(ei, E);
    h_kernel<<<zgrid, 256>>>(b1, N);
    scatter_kernel<2><<<sgrid, 256>>>(ei, E);
    gemm2_kernel<<<ggrid, 256>>>(Wl2, Wr2, b2, out, N);
}

// round 5
// speedup vs baseline: 1.3187x; 1.3187x over previous
#include <cuda_runtime.h>
#include <cuda_bf16.h>
#include <cstdint>

// GraphSAGE 2-layer.
//   p1|q1 = x @ [W_l1 | W_r1]^T          (GEMM1 tf32 tensor-core, [N,128] out)
//   s1    = scatter-add p1[src] at dst ; deg = scatter-add 1
//   h     = relu(s1/max(deg,1) + b1 + q1)
//   s2    = scatter-add h[src] at dst
//   out   = [s2*rdeg | h] @ [W_l2 | W_r2]^T + b2   (GEMM2 tf32 tensor-core)
//
// NOTE: __device__ globals are referenced ONLY inside kernels (host-side
// symbol shadows are not valid device pointers).

#define NMAX 100000

__device__ __align__(16) float g_pq  [(size_t)NMAX * 128];  // p1 (cols 0..63) | q1 (64..127)
__device__ __align__(16) float g_s1  [(size_t)NMAX * 64];
__device__ __align__(16) float g_h   [(size_t)NMAX * 64];
__device__ __align__(16) float g_s2  [(size_t)NMAX * 64];
__device__ __align__(16) float g_deg [NMAX];
__device__ __align__(16) float g_rdeg[NMAX];

// ---------------------------------------------------------------------------
// zero accumulators
// ---------------------------------------------------------------------------
__global__ void zero_kernel(int N) {
    int gid = blockIdx.x * 256 + threadIdx.x;           // N*16 threads
    float4 z = make_float4(0.f, 0.f, 0.f, 0.f);
    int n16 = N * 16;
    if (gid < n16) {
        reinterpret_cast<float4*>(g_s1)[gid] = z;
        reinterpret_cast<float4*>(g_s2)[gid] = z;
    }
    if (gid < (N + 3) / 4) {
        reinterpret_cast<float4*>(g_deg)[gid] = z;
    }
}

// ---------------------------------------------------------------------------
// tf32 tensor-core GEMM
// Block: 256 threads (8 warps, 4x2), tile 128(M) x 128(N), K chunked by 32.
// Warp tile 32x64 via m16n8k8: 2 m-tiles x 8 n-tiles, 4 k-steps per chunk.
// smem: paired-k layout so each fragment loads as one LDS.64:
//   koff(kl) = (kl & ~7) + ((kl & 3) << 1) + ((kl >> 2) & 1)   -> (k, k+4) adjacent
// LDC = 40 floats; static smem 40 KB < 48 KB default (no attribute opt-in).
// ---------------------------------------------------------------------------
#define LDC 40

__device__ __forceinline__ uint32_t f2tf32(float f) {
    uint32_t o; asm("cvt.rna.tf32.f32 %0, %1;" : "=r"(o) : "f"(f)); return o;
}
__device__ __forceinline__ int koff(int kl) {
    return (kl & ~7) + ((kl & 3) << 1) + ((kl >> 2) & 1);
}

#define MMA4(c, a, b) asm volatile( \
  "mma.sync.aligned.m16n8k8.row.col.f32.tf32.tf32.f32 " \
  "{%0,%1,%2,%3},{%4,%5,%6,%7},{%8,%9},{%0,%1,%2,%3};" \
  : "+f"(c[0]), "+f"(c[1]), "+f"(c[2]), "+f"(c[3]) \
  : "r"(a[0]), "r"(a[1]), "r"(a[2]), "r"(a[3]), "r"(b.x), "r"(b.y))

// MODE 1: A = x [N,128]; B rows: n<64 -> Wl1[n,:], else Wr1[n-64,:]; no bias; writes g_pq
// MODE 2: A cols 0..63 = s2*rdeg, 64..127 = h; B: k<64 -> Wl2, else Wr2; +bias; writes outp
template<int MODE>
__global__ __launch_bounds__(256, 2) void gemm_tc(
    const float* __restrict__ x,
    const float* __restrict__ Wl, const float* __restrict__ Wr,
    const float* __restrict__ bias, float* __restrict__ outp, int N)
{
    __shared__ uint32_t As[128 * LDC];
    __shared__ uint32_t Bs[128 * LDC];
    const int tid  = threadIdx.x;
    const int m0   = blockIdx.x * 128;
    const int lane = tid & 31, warp = tid >> 5;
    const int g    = lane >> 2, t = lane & 3;
    const int rm   = (warp >> 1) * 32;
    const int cn   = (warp & 1) * 64;

    float* dstbuf = (MODE == 1) ? g_pq : outp;   // device-side symbol ref

    float acc[2][8][4];
#pragma unroll
    for (int i = 0; i < 2; i++)
#pragma unroll
        for (int j = 0; j < 8; j++)
#pragma unroll
            for (int q = 0; q < 4; q++) acc[i][j][q] = 0.f;

#pragma unroll
    for (int kc = 0; kc < 128; kc += 32) {
        if (kc) __syncthreads();
        // ---- stage A chunk (128 rows x 32 k) ----
#pragma unroll
        for (int it = 0; it < 4; it++) {
            int f = tid + it * 256;          // 0..1023
            int row = f >> 3, q = f & 7;     // row 0..127, q = float4 index 0..7
            int gm = m0 + row;
            float4 v = make_float4(0.f, 0.f, 0.f, 0.f);
            if (MODE == 1) {
                if (gm < N)
                    v = *reinterpret_cast<const float4*>(x + (size_t)gm * 128 + kc + q * 4);
            } else {
                if (gm < N) {
                    if (kc < 64) {
                        v = *reinterpret_cast<const float4*>(g_s2 + (size_t)gm * 64 + kc + q * 4);
                        float r = g_rdeg[gm];
                        v.x *= r; v.y *= r; v.z *= r; v.w *= r;
                    } else {
                        v = *reinterpret_cast<const float4*>(g_h + (size_t)gm * 64 + (kc - 64) + q * 4);
                    }
                }
            }
            int kl = q * 4;
            uint32_t* dst = As + row * LDC;
            dst[koff(kl + 0)] = f2tf32(v.x);
            dst[koff(kl + 1)] = f2tf32(v.y);
            dst[koff(kl + 2)] = f2tf32(v.z);
            dst[koff(kl + 3)] = f2tf32(v.w);
        }
        // ---- stage B chunk (128 n x 32 k) ----
#pragma unroll
        for (int it = 0; it < 4; it++) {
            int f = tid + it * 256;
            int n = f >> 3, q = f & 7;
            const float* src;
            if (MODE == 1)
                src = (n < 64) ? (Wl + (size_t)n * 128 + kc + q * 4)
                               : (Wr + (size_t)(n - 64) * 128 + kc + q * 4);
            else
                src = ((kc < 64) ? (Wl + (size_t)n * 64 + kc)
                                 : (Wr + (size_t)n * 64 + (kc - 64))) + q * 4;
            float4 v = *reinterpret_cast<const float4*>(src);
            int kl = q * 4;
            uint32_t* dst = Bs + n * LDC;
            dst[koff(kl + 0)] = f2tf32(v.x);
            dst[koff(kl + 1)] = f2tf32(v.y);
            dst[koff(kl + 2)] = f2tf32(v.z);
            dst[koff(kl + 3)] = f2tf32(v.w);
        }
        __syncthreads();
        // ---- compute: 4 k-steps of m16n8k8 ----
#pragma unroll
        for (int s = 0; s < 4; s++) {
            uint32_t a[2][4];
#pragma unroll
            for (int mt = 0; mt < 2; mt++) {
                int m = rm + mt * 16 + g;
                uint2 lo = *reinterpret_cast<const uint2*>(As + m * LDC + s * 8 + t * 2);
                uint2 hi = *reinterpret_cast<const uint2*>(As + (m + 8) * LDC + s * 8 + t * 2);
                a[mt][0] = lo.x; a[mt][1] = hi.x; a[mt][2] = lo.y; a[mt][3] = hi.y;
            }
#pragma unroll
            for (int nt = 0; nt < 8; nt++) {
                uint2 b = *reinterpret_cast<const uint2*>(Bs + (cn + nt * 8 + g) * LDC + s * 8 + t * 2);
                MMA4(acc[0][nt], a[0], b);
                MMA4(acc[1][nt], a[1], b);
            }
        }
    }
    // ---- epilogue ----
#pragma unroll
    for (int mt = 0; mt < 2; mt++) {
#pragma unroll
        for (int nt = 0; nt < 8; nt++) {
            int row = m0 + rm + mt * 16 + g;
            int col = cn + nt * 8 + t * 2;
            float b0 = 0.f, b1 = 0.f;
            if (MODE == 2) {
                float2 bb = *reinterpret_cast<const float2*>(bias + col);
                b0 = bb.x; b1 = bb.y;
            }
            if (row < N)
                *reinterpret_cast<float2*>(dstbuf + (size_t)row * 128 + col) =
                    make_float2(acc[mt][nt][0] + b0, acc[mt][nt][1] + b1);
            if (row + 8 < N)
                *reinterpret_cast<float2*>(dstbuf + (size_t)(row + 8) * 128 + col) =
                    make_float2(acc[mt][nt][2] + b0, acc[mt][nt][3] + b1);
        }
    }
}

// ---------------------------------------------------------------------------
// scatter: 16 threads per edge, red.global.add.v4.f32 (16B vector atomics)
// LAYER 1: feat = g_pq (stride 128, p1 = first 64), out = g_s1, also count deg
// LAYER 2: feat = g_h  (stride 64),                 out = g_s2
// ---------------------------------------------------------------------------
template <int LAYER>
__global__ void scatter_kernel(const int* __restrict__ ei, int E) {
    int gid = blockIdx.x * 256 + threadIdx.x;
    int e = gid >> 4;
    if (e >= E) return;
    int part = gid & 15;
    int s = __ldg(ei + e);
    int d = __ldg(ei + E + e);
    const float* feat = (LAYER == 1) ? g_pq : g_h;
    const int stride  = (LAYER == 1) ? 128 : 64;
    float4 v = *reinterpret_cast<const float4*>(feat + (size_t)s * stride + part * 4);
    float* outp = ((LAYER == 1) ? g_s1 : g_s2) + (size_t)d * 64 + part * 4;
    asm volatile("red.global.add.v4.f32 [%0], {%1,%2,%3,%4};"
                 :: "l"(outp), "f"(v.x), "f"(v.y), "f"(v.z), "f"(v.w) : "memory");
    if (LAYER == 1 && part == 0)
        atomicAdd(&g_deg[d], 1.0f);
}

// ---------------------------------------------------------------------------
// h = relu(s1/max(deg,1) + b1 + q1) ; also store rdeg = 1/max(deg,1)
// ---------------------------------------------------------------------------
__global__ void h_kernel(const float* __restrict__ b1, int N) {
    int gid = blockIdx.x * 256 + threadIdx.x;   // N*16 threads
    int node = gid >> 4;
    if (node >= N) return;
    int part = gid & 15;
    float r = 1.0f / fmaxf(g_deg[node], 1.0f);
    if (part == 0) g_rdeg[node] = r;
    float4 sv = *reinterpret_cast<const float4*>(g_s1 + (size_t)node * 64 + part * 4);
    float4 qv = *reinterpret_cast<const float4*>(g_pq + (size_t)node * 128 + 64 + part * 4);
    float4 bv = *reinterpret_cast<const float4*>(b1 + part * 4);
    float4 hv;
    hv.x = fmaxf(sv.x * r + bv.x + qv.x, 0.f);
    hv.y = fmaxf(sv.y * r + bv.y + qv.y, 0.f);
    hv.z = fmaxf(sv.z * r + bv.z + qv.z, 0.f);
    hv.w = fmaxf(sv.w * r + bv.w + qv.w, 0.f);
    *reinterpret_cast<float4*>(g_h + (size_t)node * 64 + part * 4) = hv;
}

// ---------------------------------------------------------------------------
extern "C" void kernel_launch(void* const* d_in, const int* in_sizes, int n_in,
                              void* d_out, int out_size)
{
    const float* x   = (const float*)d_in[0];
    const int*   ei  = (const int*)  d_in[1];
    const float* Wl1 = (const float*)d_in[2];
    const float* Wr1 = (const float*)d_in[3];
    const float* b1  = (const float*)d_in[4];
    const float* Wl2 = (const float*)d_in[5];
    const float* Wr2 = (const float*)d_in[6];
    const float* b2  = (const float*)d_in[7];
    float* out = (float*)d_out;

    int N = in_sizes[0] / 128;
    int E = in_sizes[1] / 2;

    int zgrid = (N * 16 + 255) / 256;
    int ggrid = (N + 127) / 128;
    long sthreads = (long)E * 16;
    int sgrid = (int)((sthreads + 255) / 256);

    zero_kernel<<<zgrid, 256>>>(N);
    gemm_tc<1><<<ggrid, 256>>>(x, Wl1, Wr1, nullptr, nullptr, N);
    scatter_kernel<1><<<sgrid, 256>>>(ei, E);
    h_kernel<<<zgrid, 256>>>(b1, N);
    scatter_kernel<2><<<sgrid, 256>>>(ei, E);
    gemm_tc<2><<<ggrid, 256>>>(nullptr, Wl2, Wr2, b2, out, N);
}